// round 1
// baseline (speedup 1.0000x reference)
#include <cuda_runtime.h>
#include <cstdint>

// Problem constants (fixed by the reference)
#define BB   32
#define CC   128
#define HH   128
#define WW   128
#define OH   64
#define OW   64
// output plane stride (one of vals/pos_h/pos_w planes per channel block)
#define PLANE ((size_t)CC * OH * OW)   // 524288

__device__ __forceinline__ void win2x2(float a, float b, float c, float d,
                                       int row0, int col0,
                                       float& val, float& ph, float& pw) {
    // first-max argmax over order [a, b, c, d] == flat idx kh*2+kw
    float best = a; int idx = 0;
    if (b > best) { best = b; idx = 1; }
    if (c > best) { best = c; idx = 2; }
    if (d > best) { best = d; idx = 3; }
    int row = row0 + (idx >> 1);
    int col = col0 + (idx & 1);
    val = best;
    ph = (float)row * (1.0f / (float)HH);
    pw = (float)col * (1.0f / (float)WW);
}

__global__ void __launch_bounds__(256)
pap_pool_kernel(const float* __restrict__ x, float* __restrict__ out) {
    // thread -> (bc, oh, ow2): ow2 indexes a PAIR of output columns
    // total threads = B*C*OH*(OW/2) = 32*128*64*32 = 8,388,608
    unsigned tid = blockIdx.x * blockDim.x + threadIdx.x;

    unsigned ow2 = tid & 31u;          // OW/2 = 32 pairs
    unsigned oh  = (tid >> 5) & 63u;   // OH = 64
    unsigned bc  = tid >> 11;          // b*C + c, 0..4095

    // input: two float4 loads covering rows (2*oh, 2*oh+1), cols [4*ow2, 4*ow2+4)
    const float4* xr = reinterpret_cast<const float4*>(
        x + ((size_t)bc * HH + 2u * oh) * WW) + ow2;
    float4 r0 = xr[0];
    float4 r1 = xr[WW / 4];   // next row

    int row0 = 2 * (int)oh;
    int col0 = 4 * (int)ow2;     // global input col of first window

    float v0, ph0, pw0, v1, ph1, pw1;
    win2x2(r0.x, r0.y, r1.x, r1.y, row0, col0,     v0, ph0, pw0);
    win2x2(r0.z, r0.w, r1.z, r1.w, row0, col0 + 2, v1, ph1, pw1);

    // output: [B, 3C, OH, OW]; b = bc/128, c = bc%128
    unsigned b = bc >> 7;
    unsigned c = bc & 127u;
    size_t obase = (((size_t)b * 3u * CC + c) * OH + oh) * OW + 2u * ow2;

    *reinterpret_cast<float2*>(out + obase)             = make_float2(v0,  v1);
    *reinterpret_cast<float2*>(out + obase + PLANE)     = make_float2(ph0, ph1);
    *reinterpret_cast<float2*>(out + obase + 2 * PLANE) = make_float2(pw0, pw1);
}

extern "C" void kernel_launch(void* const* d_in, const int* in_sizes, int n_in,
                              void* d_out, int out_size) {
    const float* x = (const float*)d_in[0];
    float* out = (float*)d_out;
    // 8,388,608 threads total
    const unsigned nthreads = BB * CC * OH * (OW / 2);
    const unsigned block = 256;
    pap_pool_kernel<<<nthreads / block, block>>>(x, out);
}